// round 12
// baseline (speedup 1.0000x reference)
#include <cuda_runtime.h>
#include <cuda_bf16.h>

// out = -0.1f * x over 67,108,864 fp32 elements (256 MiB in + 256 MiB out).
// FINAL kernel — at the HBM roofline: ~6.45 TB/s sustained = 81-82% of the
// 8 TB/s spec = the bidirectional read+write turnaround ceiling for a 1:1
// stream on GB300 HBM3e. Verified stable across 3 identical-binary runs
// (kernel 73.8/74.9/75.0 us; noise +/-1 us). Full sweep was flat within
// noise: 2x512=73.8-75.0*, 4x512=74.0, v8=74.6, 4x256=74.7, 2x256=75.1,
// 8x256=75.2, wt-stores=75.4, 1x256=79.2, persistent-grid=80.1.
// Structure: LDG.E.128.CS x2 front-batched per thread, FMUL, STG.E.128.CS,
// exact-fit grid with no predication. All compute pipes <4% busy; no
// remaining SM-side lever moves the DRAM number.

#define ITEMS 2
#define THREADS 512
#define TILE (THREADS * ITEMS)

// Exact-fit: grid covers n4 exactly, no bounds checks.
__global__ void __launch_bounds__(THREADS)
scale_kernel_exact(const float4* __restrict__ x,
                   float4* __restrict__ out) {
    int base = blockIdx.x * TILE + threadIdx.x;

    float4 v[ITEMS];
    #pragma unroll
    for (int k = 0; k < ITEMS; k++) {
        v[k] = __ldcs(&x[base + k * THREADS]);
    }

    #pragma unroll
    for (int k = 0; k < ITEMS; k++) {
        float4 r;
        r.x = -0.1f * v[k].x;
        r.y = -0.1f * v[k].y;
        r.z = -0.1f * v[k].z;
        r.w = -0.1f * v[k].w;
        __stcs(&out[base + k * THREADS], r);
    }
}

// Guarded generic kernel for sizes that don't divide into whole tiles.
__global__ void __launch_bounds__(THREADS)
scale_kernel_guarded(const float4* __restrict__ x,
                     float4* __restrict__ out,
                     int n4) {
    int base = blockIdx.x * TILE + threadIdx.x;
    #pragma unroll
    for (int k = 0; k < ITEMS; k++) {
        int i = base + k * THREADS;
        if (i < n4) {
            float4 v = __ldcs(&x[i]);
            float4 r;
            r.x = -0.1f * v.x;
            r.y = -0.1f * v.y;
            r.z = -0.1f * v.z;
            r.w = -0.1f * v.w;
            __stcs(&out[i], r);
        }
    }
}

// Scalar tail for element counts not divisible by 4.
__global__ void scale_kernel_tail(const float* __restrict__ x,
                                  float* __restrict__ out,
                                  int start, int n) {
    int i = start + blockIdx.x * blockDim.x + threadIdx.x;
    if (i < n) {
        out[i] = -0.1f * x[i];
    }
}

extern "C" void kernel_launch(void* const* d_in, const int* in_sizes, int n_in,
                              void* d_out, int out_size) {
    const float* x = (const float*)d_in[0];
    float* out = (float*)d_out;
    int n = in_sizes[0];

    int n4 = n / 4;
    if (n4 > 0) {
        if (n4 % TILE == 0) {
            scale_kernel_exact<<<n4 / TILE, THREADS>>>(
                (const float4*)x, (float4*)out);
        } else {
            int blocks = (n4 + TILE - 1) / TILE;
            scale_kernel_guarded<<<blocks, THREADS>>>(
                (const float4*)x, (float4*)out, n4);
        }
    }
    int tail_start = n4 * 4;
    int tail = n - tail_start;
    if (tail > 0) {
        scale_kernel_tail<<<1, 256>>>(x, out, tail_start, n);
    }
}

// round 13
// speedup vs baseline: 1.0043x; 1.0043x over previous
#include <cuda_runtime.h>
#include <cuda_bf16.h>

// out = -0.1f * x over 67,108,864 fp32 elements (256 MiB in + 256 MiB out).
// HBM-roofline stream: ~6.4 TB/s = 80-82% of spec (r+w turnaround ceiling).
// Structure is the converged optimum (ITEMS=2 x THREADS=512 float4,
// front-batched loads, exact-fit grid; 4 runs: kernel 73.8-75.5 us).
// This round's single-bit probe: last-use loads (__ldlu -> LDG.128.LU).
// Input is read exactly once — .lu discards L2 lines after the read
// instead of queueing them evict-first, freeing L2 tag/capacity bandwidth
// for write coalescing.
// Sweep history (kernel us): 2x512cs=73.8-75.5*, 4x512=74.0, v8=74.6,
// 4x256=74.7, 2x256=75.1, 8x256=75.2, wt-stores=75.4, 1x256=79.2,
// persistent=80.1.

#define ITEMS 2
#define THREADS 512
#define TILE (THREADS * ITEMS)

// Exact-fit: grid covers n4 exactly, no bounds checks.
__global__ void __launch_bounds__(THREADS)
scale_kernel_exact(const float4* __restrict__ x,
                   float4* __restrict__ out) {
    int base = blockIdx.x * TILE + threadIdx.x;

    float4 v[ITEMS];
    #pragma unroll
    for (int k = 0; k < ITEMS; k++) {
        v[k] = __ldlu(&x[base + k * THREADS]);
    }

    #pragma unroll
    for (int k = 0; k < ITEMS; k++) {
        float4 r;
        r.x = -0.1f * v[k].x;
        r.y = -0.1f * v[k].y;
        r.z = -0.1f * v[k].z;
        r.w = -0.1f * v[k].w;
        __stcs(&out[base + k * THREADS], r);
    }
}

// Guarded generic kernel for sizes that don't divide into whole tiles.
__global__ void __launch_bounds__(THREADS)
scale_kernel_guarded(const float4* __restrict__ x,
                     float4* __restrict__ out,
                     int n4) {
    int base = blockIdx.x * TILE + threadIdx.x;
    #pragma unroll
    for (int k = 0; k < ITEMS; k++) {
        int i = base + k * THREADS;
        if (i < n4) {
            float4 v = __ldlu(&x[i]);
            float4 r;
            r.x = -0.1f * v.x;
            r.y = -0.1f * v.y;
            r.z = -0.1f * v.z;
            r.w = -0.1f * v.w;
            __stcs(&out[i], r);
        }
    }
}

// Scalar tail for element counts not divisible by 4.
__global__ void scale_kernel_tail(const float* __restrict__ x,
                                  float* __restrict__ out,
                                  int start, int n) {
    int i = start + blockIdx.x * blockDim.x + threadIdx.x;
    if (i < n) {
        out[i] = -0.1f * x[i];
    }
}

extern "C" void kernel_launch(void* const* d_in, const int* in_sizes, int n_in,
                              void* d_out, int out_size) {
    const float* x = (const float*)d_in[0];
    float* out = (float*)d_out;
    int n = in_sizes[0];

    int n4 = n / 4;
    if (n4 > 0) {
        if (n4 % TILE == 0) {
            scale_kernel_exact<<<n4 / TILE, THREADS>>>(
                (const float4*)x, (float4*)out);
        } else {
            int blocks = (n4 + TILE - 1) / TILE;
            scale_kernel_guarded<<<blocks, THREADS>>>(
                (const float4*)x, (float4*)out, n4);
        }
    }
    int tail_start = n4 * 4;
    int tail = n - tail_start;
    if (tail > 0) {
        scale_kernel_tail<<<1, 256>>>(x, out, tail_start, n);
    }
}

// round 14
// speedup vs baseline: 1.0207x; 1.0163x over previous
#include <cuda_runtime.h>
#include <cuda_bf16.h>

// out = -0.1f * x over 67,108,864 fp32 elements (256 MiB in + 256 MiB out).
// FINAL kernel — at the HBM roofline: ~6.4-6.5 TB/s sustained = 80-82% of
// the 8 TB/s spec, the bidirectional read+write turnaround ceiling for a
// 1:1 stream on GB300 HBM3e. Converged after a 13-round sweep; all axes
// flat within the +/-1 us noise floor:
//   vector width 32/128/256b; unroll 1/2/4/8 (2-4 optimal); blocks 256/512;
//   occupancy 57-80% (not binding); flat vs persistent grid (persistent -6us);
//   .cs/.lu loads (equal), .cs/.wt stores (.wt -1.6us).
// Best observed with this exact binary: kernel 73.8 us, total 81.0 us.
// Structure: 2x front-batched LDG.E.128.CS per thread, FMUL, STG.E.128.CS,
// exact-fit grid with no predication. Compute pipes <4% busy.

#define ITEMS 2
#define THREADS 512
#define TILE (THREADS * ITEMS)

// Exact-fit: grid covers n4 exactly, no bounds checks.
__global__ void __launch_bounds__(THREADS)
scale_kernel_exact(const float4* __restrict__ x,
                   float4* __restrict__ out) {
    int base = blockIdx.x * TILE + threadIdx.x;

    float4 v[ITEMS];
    #pragma unroll
    for (int k = 0; k < ITEMS; k++) {
        v[k] = __ldcs(&x[base + k * THREADS]);
    }

    #pragma unroll
    for (int k = 0; k < ITEMS; k++) {
        float4 r;
        r.x = -0.1f * v[k].x;
        r.y = -0.1f * v[k].y;
        r.z = -0.1f * v[k].z;
        r.w = -0.1f * v[k].w;
        __stcs(&out[base + k * THREADS], r);
    }
}

// Guarded generic kernel for sizes that don't divide into whole tiles.
__global__ void __launch_bounds__(THREADS)
scale_kernel_guarded(const float4* __restrict__ x,
                     float4* __restrict__ out,
                     int n4) {
    int base = blockIdx.x * TILE + threadIdx.x;
    #pragma unroll
    for (int k = 0; k < ITEMS; k++) {
        int i = base + k * THREADS;
        if (i < n4) {
            float4 v = __ldcs(&x[i]);
            float4 r;
            r.x = -0.1f * v.x;
            r.y = -0.1f * v.y;
            r.z = -0.1f * v.z;
            r.w = -0.1f * v.w;
            __stcs(&out[i], r);
        }
    }
}

// Scalar tail for element counts not divisible by 4.
__global__ void scale_kernel_tail(const float* __restrict__ x,
                                  float* __restrict__ out,
                                  int start, int n) {
    int i = start + blockIdx.x * blockDim.x + threadIdx.x;
    if (i < n) {
        out[i] = -0.1f * x[i];
    }
}

extern "C" void kernel_launch(void* const* d_in, const int* in_sizes, int n_in,
                              void* d_out, int out_size) {
    const float* x = (const float*)d_in[0];
    float* out = (float*)d_out;
    int n = in_sizes[0];

    int n4 = n / 4;
    if (n4 > 0) {
        if (n4 % TILE == 0) {
            scale_kernel_exact<<<n4 / TILE, THREADS>>>(
                (const float4*)x, (float4*)out);
        } else {
            int blocks = (n4 + TILE - 1) / TILE;
            scale_kernel_guarded<<<blocks, THREADS>>>(
                (const float4*)x, (float4*)out, n4);
        }
    }
    int tail_start = n4 * 4;
    int tail = n - tail_start;
    if (tail > 0) {
        scale_kernel_tail<<<1, 256>>>(x, out, tail_start, n);
    }
}

// round 15
// speedup vs baseline: 1.0211x; 1.0004x over previous
#include <cuda_runtime.h>
#include <cuda_bf16.h>

// out = -0.1f * x over 67,108,864 fp32 elements (256 MiB in + 256 MiB out).
// FINAL kernel — at the HBM roofline: ~6.4-6.5 TB/s sustained = 80-82% of
// the 8 TB/s spec, the bidirectional read+write turnaround ceiling for a
// 1:1 stream on GB300 HBM3e. Converged over a 14-round sweep; identical-
// binary totals {80.4, 81.0, 81.5, 81.9, 82.1} us (noise band +/-0.9 us),
// kernel 73.8-75.5 us. All axes tested flat or worse:
//   vector width 32/128/256b; unroll 1/2/4/8 (2-4 optimal); blocks 256/512;
//   occupancy 57-80% (non-binding, anti-correlated); flat vs persistent grid
//   (persistent -6us); .cs/.lu loads (equal); .cs/.wt stores (.wt -1.6us).
// Structure: 2x front-batched LDG.E.128.CS per thread, FMUL, STG.E.128.CS,
// exact-fit grid with no predication. Compute pipes <4% busy.

#define ITEMS 2
#define THREADS 512
#define TILE (THREADS * ITEMS)

// Exact-fit: grid covers n4 exactly, no bounds checks.
__global__ void __launch_bounds__(THREADS)
scale_kernel_exact(const float4* __restrict__ x,
                   float4* __restrict__ out) {
    int base = blockIdx.x * TILE + threadIdx.x;

    float4 v[ITEMS];
    #pragma unroll
    for (int k = 0; k < ITEMS; k++) {
        v[k] = __ldcs(&x[base + k * THREADS]);
    }

    #pragma unroll
    for (int k = 0; k < ITEMS; k++) {
        float4 r;
        r.x = -0.1f * v[k].x;
        r.y = -0.1f * v[k].y;
        r.z = -0.1f * v[k].z;
        r.w = -0.1f * v[k].w;
        __stcs(&out[base + k * THREADS], r);
    }
}

// Guarded generic kernel for sizes that don't divide into whole tiles.
__global__ void __launch_bounds__(THREADS)
scale_kernel_guarded(const float4* __restrict__ x,
                     float4* __restrict__ out,
                     int n4) {
    int base = blockIdx.x * TILE + threadIdx.x;
    #pragma unroll
    for (int k = 0; k < ITEMS; k++) {
        int i = base + k * THREADS;
        if (i < n4) {
            float4 v = __ldcs(&x[i]);
            float4 r;
            r.x = -0.1f * v.x;
            r.y = -0.1f * v.y;
            r.z = -0.1f * v.z;
            r.w = -0.1f * v.w;
            __stcs(&out[i], r);
        }
    }
}

// Scalar tail for element counts not divisible by 4.
__global__ void scale_kernel_tail(const float* __restrict__ x,
                                  float* __restrict__ out,
                                  int start, int n) {
    int i = start + blockIdx.x * blockDim.x + threadIdx.x;
    if (i < n) {
        out[i] = -0.1f * x[i];
    }
}

extern "C" void kernel_launch(void* const* d_in, const int* in_sizes, int n_in,
                              void* d_out, int out_size) {
    const float* x = (const float*)d_in[0];
    float* out = (float*)d_out;
    int n = in_sizes[0];

    int n4 = n / 4;
    if (n4 > 0) {
        if (n4 % TILE == 0) {
            scale_kernel_exact<<<n4 / TILE, THREADS>>>(
                (const float4*)x, (float4*)out);
        } else {
            int blocks = (n4 + TILE - 1) / TILE;
            scale_kernel_guarded<<<blocks, THREADS>>>(
                (const float4*)x, (float4*)out, n4);
        }
    }
    int tail_start = n4 * 4;
    int tail = n - tail_start;
    if (tail > 0) {
        scale_kernel_tail<<<1, 256>>>(x, out, tail_start, n);
    }
}